// round 5
// baseline (speedup 1.0000x reference)
#include <cuda_runtime.h>
#include <math.h>

// Shapes (hardcoded from reference setup_inputs)
#define Bn   64
#define Nn   1025
#define Dn   1024
#define Cn   64

// Scratch (device globals; no runtime allocation)
__device__ __align__(16) float g_h[(size_t)Bn * Nn * Cn];     // post LN+GEMM1   (B,N,C)
__device__ __align__(16) float g_sp[(size_t)Bn * 1024 * Cn];  // post depthwise  (B,HW,C)
__device__ __align__(16) float g_act[(size_t)Bn * Nn * Cn];   // post proj+gelu  (B,N,C)

// ---------- packed f32x2 helpers (FFMA2 path: rt 1/SMSP vs rt 2 for FFMA-3reg) ----------
static __device__ __forceinline__ unsigned long long pk2(float a, float b) {
    unsigned long long r;
    asm("mov.b64 %0, {%1,%2};" : "=l"(r) : "f"(a), "f"(b));
    return r;
}
static __device__ __forceinline__ void upk2(unsigned long long v, float& a, float& b) {
    asm("mov.b64 {%0,%1}, %2;" : "=f"(a), "=f"(b) : "l"(v));
}
static __device__ __forceinline__ void fma2(unsigned long long& d, unsigned long long a,
                                            unsigned long long b) {
    asm("fma.rn.f32x2 %0, %1, %2, %0;" : "+l"(d) : "l"(a), "l"(b));
}

static __device__ __forceinline__ float gelu_exact(float t) {
    return 0.5f * t * (1.0f + erff(t * 0.70710678118654752f));
}

// ======================================================================
// Kernel 1: LayerNorm + gamma-mix + GEMM1 (y @ w1 + b1) -> g_h
// 4 rows per block, 256 threads. f32x2 inner product.
// ======================================================================
__global__ __launch_bounds__(256) void k1_ln_gemm1(
    const float* __restrict__ x, const float* __restrict__ lnw, const float* __restrict__ lnb,
    const float* __restrict__ gam, const float* __restrict__ gmx,
    const float* __restrict__ w1, const float* __restrict__ b1)
{
    __shared__ unsigned long long syd[4 * 1024];  // 32KB: duplicated y; later aliased as reduce buf
    __shared__ float2 red4[4][8];

    const int tid = threadIdx.x;
    const int row0 = blockIdx.x * 4;

    int bb[4], nn[4];
#pragma unroll
    for (int r = 0; r < 4; r++) {
        int row = row0 + r;
        bb[r] = row / Nn;
        nn[r] = row - bb[r] * Nn;
    }

    // ---- load x rows + partial LN stats ----
    float4 v[4];
    float s[4], q[4];
#pragma unroll
    for (int r = 0; r < 4; r++) {
        const float4* p = (const float4*)(x + ((size_t)(nn[r] * Bn + bb[r]) << 10));
        float4 t = p[tid];
        v[r] = t;
        s[r] = t.x + t.y + t.z + t.w;
        q[r] = t.x * t.x + t.y * t.y + t.z * t.z + t.w * t.w;
    }
#pragma unroll
    for (int o = 16; o; o >>= 1) {
#pragma unroll
        for (int r = 0; r < 4; r++) {
            s[r] += __shfl_xor_sync(0xffffffffu, s[r], o);
            q[r] += __shfl_xor_sync(0xffffffffu, q[r], o);
        }
    }
    const int wid = tid >> 5;
    if ((tid & 31) == 0) {
#pragma unroll
        for (int r = 0; r < 4; r++) red4[r][wid] = make_float2(s[r], q[r]);
    }
    __syncthreads();

    float mu[4], rs[4];
#pragma unroll
    for (int r = 0; r < 4; r++) {
        float a = 0.f, c = 0.f;
#pragma unroll
        for (int w = 0; w < 8; w++) { a += red4[r][w].x; c += red4[r][w].y; }
        mu[r] = a * (1.0f / 1024.0f);
        float var = c * (1.0f / 1024.0f) - mu[r] * mu[r];
        rs[r] = rsqrtf(var + 1e-5f);
    }

    // ---- y = (ln * gamma) + x * gammax, stored duplicated for f32x2 ----
    const float4 lw = ((const float4*)lnw)[tid];
    const float4 lb = ((const float4*)lnb)[tid];
    const float4 gm = ((const float4*)gam)[tid];
    const float4 gx = ((const float4*)gmx)[tid];
#pragma unroll
    for (int r = 0; r < 4; r++) {
        float4 t = v[r];
        float y0 = ((t.x - mu[r]) * rs[r] * lw.x + lb.x) * gm.x + t.x * gx.x;
        float y1 = ((t.y - mu[r]) * rs[r] * lw.y + lb.y) * gm.y + t.y * gx.y;
        float y2 = ((t.z - mu[r]) * rs[r] * lw.z + lb.z) * gm.z + t.z * gx.z;
        float y3 = ((t.w - mu[r]) * rs[r] * lw.w + lb.w) * gm.w + t.w * gx.w;
        unsigned long long* dst = syd + r * 1024 + tid * 4;
        dst[0] = pk2(y0, y0);
        dst[1] = pk2(y1, y1);
        dst[2] = pk2(y2, y2);
        dst[3] = pk2(y3, y3);
    }
    __syncthreads();

    // ---- GEMM: thread owns (d-chunk of 64, 4 c's) x 4 rows ----
    const int gidx = tid >> 4;          // 0..15 -> d range [gidx*64, +64)
    const int c0 = (tid & 15) * 4;      // 0..60
    unsigned long long acc[4][2] = {};
    const float4* w1p = (const float4*)w1;
    const int dbase = gidx * 64;
#pragma unroll 4
    for (int dd = 0; dd < 64; dd++) {
        int d = dbase + dd;
        float4 w = w1p[d * 16 + (c0 >> 2)];
        unsigned long long wl = pk2(w.x, w.y), wh = pk2(w.z, w.w);
#pragma unroll
        for (int r = 0; r < 4; r++) {
            unsigned long long yy = syd[r * 1024 + d];
            fma2(acc[r][0], yy, wl);
            fma2(acc[r][1], yy, wh);
        }
    }
    __syncthreads();

    // ---- cross-group reduction (reuse syd as float buffer) ----
    float* red = (float*)syd;  // 4*16*64 floats = 16KB
#pragma unroll
    for (int r = 0; r < 4; r++) {
        float a0, a1, a2, a3;
        upk2(acc[r][0], a0, a1);
        upk2(acc[r][1], a2, a3);
        *(float4*)(red + ((r * 16 + gidx) * 64 + c0)) = make_float4(a0, a1, a2, a3);
    }
    __syncthreads();

    const int c = tid & 63;
    const int r2 = tid >> 6;
    float sum = b1[c];
#pragma unroll
    for (int g = 0; g < 16; g++) sum += red[(r2 * 16 + g) * 64 + c];
    g_h[((size_t)bb[r2] * Nn + nn[r2]) * 64 + c] = sum;
}

// ======================================================================
// Kernel 2: depthwise 3x3 + 5x5 + 7x7, averaged, + identity -> g_sp
// Block: (4 channels, 1 batch image). smem tile 38x38x4 with zero halo=3.
// ======================================================================
__global__ __launch_bounds__(256) void k2_dwconv(
    const float* __restrict__ w3, const float* __restrict__ b3,
    const float* __restrict__ w5, const float* __restrict__ b5,
    const float* __restrict__ w7, const float* __restrict__ b7)
{
    __shared__ __align__(16) float tile[38 * 38 * 4];  // ~23KB
    __shared__ float wk[4 * 83];

    const int tid = threadIdx.x;
    const int cg = blockIdx.x;   // channel group 0..15
    const int b = blockIdx.y;    // batch 0..63

    // weights: layout wk[ch*83 + j], j: [0,9)=3x3, [9,34)=5x5, [34,83)=7x7
    for (int i = tid; i < 4 * 83; i += 256) {
        int ch = i / 83, j = i - ch * 83;
        int c = cg * 4 + ch;
        float wv;
        if (j < 9)       wv = w3[c * 9 + j];
        else if (j < 34) wv = w5[c * 25 + (j - 9)];
        else             wv = w7[c * 49 + (j - 34)];
        wk[i] = wv;
    }

    const float* src = g_h + ((size_t)b * Nn + 1) * 64 + cg * 4;
    for (int idx = tid; idx < 38 * 38; idx += 256) {
        int rr = idx / 38, cc = idx - rr * 38;
        int gy = rr - 3, gx = cc - 3;
        float4 val = make_float4(0.f, 0.f, 0.f, 0.f);
        if ((unsigned)gy < 32u && (unsigned)gx < 32u)
            val = *(const float4*)(src + (size_t)(gy * 32 + gx) * 64);
        *(float4*)&tile[idx * 4] = val;
    }
    __syncthreads();

    const int ch = tid & 3;
    const int col = (tid >> 2) & 31;
    const int half = tid >> 7;       // 0/1
    const int row0 = half * 16;

    float acc[16];
#pragma unroll
    for (int k = 0; k < 16; k++) acc[k] = 0.f;

    const float* wc = wk + ch * 83;

#define CONV_TAPS(RAD, WOFF, KS)                                                   \
    for (int dy = -(RAD); dy <= (RAD); dy++) {                                     \
        for (int dx = -(RAD); dx <= (RAD); dx++) {                                 \
            float wv = wc[(WOFF) + (dy + (RAD)) * (KS) + (dx + (RAD))];            \
            const float* tp = tile + (((row0 + 3 + dy) * 38) + (col + 3 + dx)) * 4 + ch; \
            _Pragma("unroll")                                                      \
            for (int k = 0; k < 16; k++) acc[k] += tp[k * 152] * wv;               \
        }                                                                          \
    }

    CONV_TAPS(1, 0, 3)
    CONV_TAPS(2, 9, 5)
    CONV_TAPS(3, 34, 7)
#undef CONV_TAPS

    const int c = cg * 4 + ch;
    const float bsum = (b3[c] + b5[c] + b7[c]) * (1.0f / 3.0f);
    float* dst = g_sp + ((size_t)b * 1024) * 64 + c;
    const float* ctr = tile + ((row0 + 3) * 38 + col + 3) * 4 + ch;
#pragma unroll
    for (int k = 0; k < 16; k++) {
        float o = acc[k] * (1.0f / 3.0f) + bsum + ctr[k * 152];
        dst[(size_t)((row0 + k) * 32 + col) * 64] = o;
    }
}

// ======================================================================
// Kernel 3: 1x1 proj + residual + exact GELU -> g_act (spatial tokens)
// Block: 32 positions of one image; 8-position register blocking.
// ======================================================================
__global__ __launch_bounds__(256) void k3_proj_gelu(
    const float* __restrict__ pw, const float* __restrict__ pb)
{
    __shared__ float pws[64 * 65];   // padded stride 65: conflict-free
    __shared__ float ssp[32 * 64];

    const int tid = threadIdx.x;
    const int b = blockIdx.x >> 5;
    const int pbase = (blockIdx.x & 31) * 32;

    for (int i = tid; i < 4096; i += 256)
        pws[(i >> 6) * 65 + (i & 63)] = pw[i];   // pws[o][k] = proj_w[o][k]

    const float* src = g_sp + ((size_t)b * 1024 + pbase) * 64;
    for (int i = tid; i < 2048; i += 256) ssp[i] = src[i];
    __syncthreads();

    const int c = tid & 63;
    const int pg = tid >> 6;  // 0..3, each handles 8 positions
    float acc[8];
#pragma unroll
    for (int j = 0; j < 8; j++) acc[j] = 0.f;

    const float* wr = pws + c * 65;
    const float* sr = ssp + pg * 8 * 64;
#pragma unroll 8
    for (int k = 0; k < 64; k++) {
        float wv = wr[k];
#pragma unroll
        for (int j = 0; j < 8; j++) acc[j] += sr[j * 64 + k] * wv;
    }

    const float pbv = pb[c];
    float* dst = g_act + ((size_t)b * Nn + 1 + pbase + pg * 8) * 64 + c;
#pragma unroll
    for (int j = 0; j < 8; j++) {
        float t = sr[j * 64 + c] + acc[j] + pbv;
        dst[(size_t)j * 64] = gelu_exact(t);
    }
}

// CLS token: gelu only (skips spatial path)
__global__ void k_cls_gelu() {
    int i = blockIdx.x * 256 + threadIdx.x;
    if (i < Bn * Cn) {
        int b = i >> 6, c = i & 63;
        size_t off = (size_t)b * Nn * 64 + c;
        g_act[off] = gelu_exact(g_h[off]);
    }
}

// ======================================================================
// Kernel 4: GEMM2 (g_act @ w2 + b2) + residual x -> out (N,B,D layout)
// 4 rows per block, f32x2 inner product, w2 L1-resident.
// ======================================================================
__global__ __launch_bounds__(256) void k4_gemm2(
    const float* __restrict__ x, const float* __restrict__ w2,
    const float* __restrict__ b2, float* __restrict__ out)
{
    __shared__ unsigned long long sgd[4 * 64];

    const int tid = threadIdx.x;
    const int row0 = blockIdx.x * 4;

    {
        int r = tid >> 6, c = tid & 63;
        int row = row0 + r;
        int b = row / Nn, n = row - b * Nn;
        float gv = g_act[((size_t)b * Nn + n) * 64 + c];
        sgd[tid] = pk2(gv, gv);
    }
    __syncthreads();

    const int d0 = tid * 4;
    const float4 b2v = *(const float4*)(b2 + d0);
    unsigned long long acc[4][2] = {};
    const float4* w2p = (const float4*)w2;
#pragma unroll 4
    for (int k = 0; k < 64; k++) {
        float4 w = w2p[k * 256 + tid];
        unsigned long long wl = pk2(w.x, w.y), wh = pk2(w.z, w.w);
#pragma unroll
        for (int r = 0; r < 4; r++) {
            unsigned long long g2 = sgd[r * 64 + k];
            fma2(acc[r][0], g2, wl);
            fma2(acc[r][1], g2, wh);
        }
    }

#pragma unroll
    for (int r = 0; r < 4; r++) {
        int row = row0 + r;
        int b = row / Nn, n = row - b * Nn;
        size_t off = ((size_t)(n * Bn + b) << 10) + d0;
        float4 xv = *(const float4*)(x + off);
        float a0, a1, a2, a3;
        upk2(acc[r][0], a0, a1);
        upk2(acc[r][1], a2, a3);
        float4 o;
        o.x = xv.x + b2v.x + a0;
        o.y = xv.y + b2v.y + a1;
        o.z = xv.z + b2v.z + a2;
        o.w = xv.w + b2v.w + a3;
        *(float4*)(out + off) = o;
    }
}

// ======================================================================
extern "C" void kernel_launch(void* const* d_in, const int* in_sizes, int n_in,
                              void* d_out, int out_size)
{
    (void)in_sizes; (void)n_in; (void)out_size;
    const float* x     = (const float*)d_in[0];
    const float* ln_w  = (const float*)d_in[1];
    const float* ln_b  = (const float*)d_in[2];
    const float* gamma = (const float*)d_in[3];
    const float* gmx   = (const float*)d_in[4];
    const float* w1    = (const float*)d_in[5];
    const float* b1    = (const float*)d_in[6];
    const float* w2    = (const float*)d_in[7];
    const float* b2    = (const float*)d_in[8];
    const float* dw3w  = (const float*)d_in[9];
    const float* dw3b  = (const float*)d_in[10];
    const float* dw5w  = (const float*)d_in[11];
    const float* dw5b  = (const float*)d_in[12];
    const float* dw7w  = (const float*)d_in[13];
    const float* dw7b  = (const float*)d_in[14];
    const float* projw = (const float*)d_in[15];
    const float* projb = (const float*)d_in[16];
    float* out = (float*)d_out;

    // 65600 rows total, 4 per block
    k1_ln_gemm1<<<16400, 256>>>(x, ln_w, ln_b, gamma, gmx, w1, b1);
    k2_dwconv<<<dim3(16, 64), 256>>>(dw3w, dw3b, dw5w, dw5b, dw7w, dw7b);
    k_cls_gelu<<<16, 256>>>();
    k3_proj_gelu<<<2048, 256>>>(projw, projb);
    k4_gemm2<<<16400, 256>>>(x, w2, b2, out);
}

// round 6
// speedup vs baseline: 1.5740x; 1.5740x over previous
#include <cuda_runtime.h>
#include <math.h>

// Shapes (hardcoded from reference setup_inputs)
#define Bn   64
#define Nn   1025
#define Dn   1024
#define Cn   64

// Scratch (device globals; no runtime allocation)
__device__ __align__(16) float g_h[(size_t)Bn * Nn * Cn];     // post LN+GEMM1   (B,N,C)
__device__ __align__(16) float g_sp[(size_t)Bn * 1024 * Cn];  // post depthwise  (B,HW,C)
__device__ __align__(16) float g_act[(size_t)Bn * Nn * Cn];   // post proj+gelu  (B,N,C)

// ---------- packed f32x2 helpers (FFMA2 path: rt 1/SMSP vs rt 2 for FFMA-3reg) ----------
static __device__ __forceinline__ unsigned long long pk2(float a, float b) {
    unsigned long long r;
    asm("mov.b64 %0, {%1,%2};" : "=l"(r) : "f"(a), "f"(b));
    return r;
}
static __device__ __forceinline__ void upk2(unsigned long long v, float& a, float& b) {
    asm("mov.b64 {%0,%1}, %2;" : "=f"(a), "=f"(b) : "l"(v));
}
static __device__ __forceinline__ void fma2(unsigned long long& d, unsigned long long a,
                                            unsigned long long b) {
    asm("fma.rn.f32x2 %0, %1, %2, %0;" : "+l"(d) : "l"(a), "l"(b));
}

static __device__ __forceinline__ float gelu_exact(float t) {
    return 0.5f * t * (1.0f + erff(t * 0.70710678118654752f));
}

// ======================================================================
// Kernel 1: LayerNorm + gamma-mix + GEMM1 (y @ w1 + b1) -> g_h
// 4 rows per block, 256 threads. f32x2 inner product.
// ======================================================================
__global__ __launch_bounds__(256) void k1_ln_gemm1(
    const float* __restrict__ x, const float* __restrict__ lnw, const float* __restrict__ lnb,
    const float* __restrict__ gam, const float* __restrict__ gmx,
    const float* __restrict__ w1, const float* __restrict__ b1)
{
    __shared__ unsigned long long syd[4 * 1024];  // 32KB: duplicated y; later aliased as reduce buf
    __shared__ float2 red4[4][8];

    const int tid = threadIdx.x;
    const int row0 = blockIdx.x * 4;

    int bb[4], nn[4];
#pragma unroll
    for (int r = 0; r < 4; r++) {
        int row = row0 + r;
        bb[r] = row / Nn;
        nn[r] = row - bb[r] * Nn;
    }

    // ---- load x rows + partial LN stats ----
    float4 v[4];
    float s[4], q[4];
#pragma unroll
    for (int r = 0; r < 4; r++) {
        const float4* p = (const float4*)(x + ((size_t)(nn[r] * Bn + bb[r]) << 10));
        float4 t = p[tid];
        v[r] = t;
        s[r] = t.x + t.y + t.z + t.w;
        q[r] = t.x * t.x + t.y * t.y + t.z * t.z + t.w * t.w;
    }
#pragma unroll
    for (int o = 16; o; o >>= 1) {
#pragma unroll
        for (int r = 0; r < 4; r++) {
            s[r] += __shfl_xor_sync(0xffffffffu, s[r], o);
            q[r] += __shfl_xor_sync(0xffffffffu, q[r], o);
        }
    }
    const int wid = tid >> 5;
    if ((tid & 31) == 0) {
#pragma unroll
        for (int r = 0; r < 4; r++) red4[r][wid] = make_float2(s[r], q[r]);
    }
    __syncthreads();

    float mu[4], rs[4];
#pragma unroll
    for (int r = 0; r < 4; r++) {
        float a = 0.f, c = 0.f;
#pragma unroll
        for (int w = 0; w < 8; w++) { a += red4[r][w].x; c += red4[r][w].y; }
        mu[r] = a * (1.0f / 1024.0f);
        float var = c * (1.0f / 1024.0f) - mu[r] * mu[r];
        rs[r] = rsqrtf(var + 1e-5f);
    }

    // ---- y = (ln * gamma) + x * gammax, stored duplicated for f32x2 ----
    const float4 lw = ((const float4*)lnw)[tid];
    const float4 lb = ((const float4*)lnb)[tid];
    const float4 gm = ((const float4*)gam)[tid];
    const float4 gx = ((const float4*)gmx)[tid];
#pragma unroll
    for (int r = 0; r < 4; r++) {
        float4 t = v[r];
        float y0 = ((t.x - mu[r]) * rs[r] * lw.x + lb.x) * gm.x + t.x * gx.x;
        float y1 = ((t.y - mu[r]) * rs[r] * lw.y + lb.y) * gm.y + t.y * gx.y;
        float y2 = ((t.z - mu[r]) * rs[r] * lw.z + lb.z) * gm.z + t.z * gx.z;
        float y3 = ((t.w - mu[r]) * rs[r] * lw.w + lb.w) * gm.w + t.w * gx.w;
        unsigned long long* dst = syd + r * 1024 + tid * 4;
        dst[0] = pk2(y0, y0);
        dst[1] = pk2(y1, y1);
        dst[2] = pk2(y2, y2);
        dst[3] = pk2(y3, y3);
    }
    __syncthreads();

    // ---- GEMM: thread owns (d-chunk of 64, 4 c's) x 4 rows ----
    const int gidx = tid >> 4;          // 0..15 -> d range [gidx*64, +64)
    const int c0 = (tid & 15) * 4;      // 0..60
    unsigned long long acc[4][2] = {};
    const float4* w1p = (const float4*)w1;
    const int dbase = gidx * 64;
#pragma unroll 4
    for (int dd = 0; dd < 64; dd++) {
        int d = dbase + dd;
        float4 w = w1p[d * 16 + (c0 >> 2)];
        unsigned long long wl = pk2(w.x, w.y), wh = pk2(w.z, w.w);
#pragma unroll
        for (int r = 0; r < 4; r++) {
            unsigned long long yy = syd[r * 1024 + d];
            fma2(acc[r][0], yy, wl);
            fma2(acc[r][1], yy, wh);
        }
    }
    __syncthreads();

    // ---- cross-group reduction (reuse syd as float buffer) ----
    float* red = (float*)syd;  // 4*16*64 floats = 16KB
#pragma unroll
    for (int r = 0; r < 4; r++) {
        float a0, a1, a2, a3;
        upk2(acc[r][0], a0, a1);
        upk2(acc[r][1], a2, a3);
        *(float4*)(red + ((r * 16 + gidx) * 64 + c0)) = make_float4(a0, a1, a2, a3);
    }
    __syncthreads();

    const int c = tid & 63;
    const int r2 = tid >> 6;
    float sum = b1[c];
#pragma unroll
    for (int g = 0; g < 16; g++) sum += red[(r2 * 16 + g) * 64 + c];
    g_h[((size_t)bb[r2] * Nn + nn[r2]) * 64 + c] = sum;
}

// ======================================================================
// Kernel 2: depthwise 3x3 + 5x5 + 7x7, averaged, + identity -> g_sp
// Block: (4 channels, 1 batch image). smem tile 38x38x4 with zero halo=3.
// ======================================================================
__global__ __launch_bounds__(256) void k2_dwconv(
    const float* __restrict__ w3, const float* __restrict__ b3,
    const float* __restrict__ w5, const float* __restrict__ b5,
    const float* __restrict__ w7, const float* __restrict__ b7)
{
    __shared__ __align__(16) float tile[38 * 38 * 4];  // ~23KB
    __shared__ float wk[4 * 83];

    const int tid = threadIdx.x;
    const int cg = blockIdx.x;   // channel group 0..15
    const int b = blockIdx.y;    // batch 0..63

    // weights: layout wk[ch*83 + j], j: [0,9)=3x3, [9,34)=5x5, [34,83)=7x7
    for (int i = tid; i < 4 * 83; i += 256) {
        int ch = i / 83, j = i - ch * 83;
        int c = cg * 4 + ch;
        float wv;
        if (j < 9)       wv = w3[c * 9 + j];
        else if (j < 34) wv = w5[c * 25 + (j - 9)];
        else             wv = w7[c * 49 + (j - 34)];
        wk[i] = wv;
    }

    const float* src = g_h + ((size_t)b * Nn + 1) * 64 + cg * 4;
    for (int idx = tid; idx < 38 * 38; idx += 256) {
        int rr = idx / 38, cc = idx - rr * 38;
        int gy = rr - 3, gx = cc - 3;
        float4 val = make_float4(0.f, 0.f, 0.f, 0.f);
        if ((unsigned)gy < 32u && (unsigned)gx < 32u)
            val = *(const float4*)(src + (size_t)(gy * 32 + gx) * 64);
        *(float4*)&tile[idx * 4] = val;
    }
    __syncthreads();

    const int ch = tid & 3;
    const int col = (tid >> 2) & 31;
    const int half = tid >> 7;       // 0/1
    const int row0 = half * 16;

    float acc[16];
#pragma unroll
    for (int k = 0; k < 16; k++) acc[k] = 0.f;

    const float* wc = wk + ch * 83;

#define CONV_TAPS(RAD, WOFF, KS)                                                   \
    for (int dy = -(RAD); dy <= (RAD); dy++) {                                     \
        for (int dx = -(RAD); dx <= (RAD); dx++) {                                 \
            float wv = wc[(WOFF) + (dy + (RAD)) * (KS) + (dx + (RAD))];            \
            const float* tp = tile + (((row0 + 3 + dy) * 38) + (col + 3 + dx)) * 4 + ch; \
            _Pragma("unroll")                                                      \
            for (int k = 0; k < 16; k++) acc[k] += tp[k * 152] * wv;               \
        }                                                                          \
    }

    CONV_TAPS(1, 0, 3)
    CONV_TAPS(2, 9, 5)
    CONV_TAPS(3, 34, 7)
#undef CONV_TAPS

    const int c = cg * 4 + ch;
    const float bsum = (b3[c] + b5[c] + b7[c]) * (1.0f / 3.0f);
    float* dst = g_sp + ((size_t)b * 1024) * 64 + c;
    const float* ctr = tile + ((row0 + 3) * 38 + col + 3) * 4 + ch;
#pragma unroll
    for (int k = 0; k < 16; k++) {
        float o = acc[k] * (1.0f / 3.0f) + bsum + ctr[k * 152];
        dst[(size_t)((row0 + k) * 32 + col) * 64] = o;
    }
}

// ======================================================================
// Kernel 3: 1x1 proj + residual + exact GELU -> g_act (spatial tokens)
// Block: 32 positions of one image; 8-position register blocking.
// ======================================================================
__global__ __launch_bounds__(256) void k3_proj_gelu(
    const float* __restrict__ pw, const float* __restrict__ pb)
{
    __shared__ float pws[64 * 65];   // padded stride 65: conflict-free
    __shared__ float ssp[32 * 64];

    const int tid = threadIdx.x;
    const int b = blockIdx.x >> 5;
    const int pbase = (blockIdx.x & 31) * 32;

    for (int i = tid; i < 4096; i += 256)
        pws[(i >> 6) * 65 + (i & 63)] = pw[i];   // pws[o][k] = proj_w[o][k]

    const float* src = g_sp + ((size_t)b * 1024 + pbase) * 64;
    for (int i = tid; i < 2048; i += 256) ssp[i] = src[i];
    __syncthreads();

    const int c = tid & 63;
    const int pg = tid >> 6;  // 0..3, each handles 8 positions
    float acc[8];
#pragma unroll
    for (int j = 0; j < 8; j++) acc[j] = 0.f;

    const float* wr = pws + c * 65;
    const float* sr = ssp + pg * 8 * 64;
#pragma unroll 8
    for (int k = 0; k < 64; k++) {
        float wv = wr[k];
#pragma unroll
        for (int j = 0; j < 8; j++) acc[j] += sr[j * 64 + k] * wv;
    }

    const float pbv = pb[c];
    float* dst = g_act + ((size_t)b * Nn + 1 + pbase + pg * 8) * 64 + c;
#pragma unroll
    for (int j = 0; j < 8; j++) {
        float t = sr[j * 64 + c] + acc[j] + pbv;
        dst[(size_t)j * 64] = gelu_exact(t);
    }
}

// CLS token: gelu only (skips spatial path)
__global__ void k_cls_gelu() {
    int i = blockIdx.x * 256 + threadIdx.x;
    if (i < Bn * Cn) {
        int b = i >> 6, c = i & 63;
        size_t off = (size_t)b * Nn * 64 + c;
        g_act[off] = gelu_exact(g_h[off]);
    }
}

// ======================================================================
// Kernel 4: GEMM2 (g_act @ w2 + b2) + residual x -> out (N,B,D layout)
// 4 rows per block, f32x2 inner product, w2 L1-resident.
// ======================================================================
__global__ __launch_bounds__(256) void k4_gemm2(
    const float* __restrict__ x, const float* __restrict__ w2,
    const float* __restrict__ b2, float* __restrict__ out)
{
    __shared__ unsigned long long sgd[4 * 64];

    const int tid = threadIdx.x;
    const int row0 = blockIdx.x * 4;

    {
        int r = tid >> 6, c = tid & 63;
        int row = row0 + r;
        int b = row / Nn, n = row - b * Nn;
        float gv = g_act[((size_t)b * Nn + n) * 64 + c];
        sgd[tid] = pk2(gv, gv);
    }
    __syncthreads();

    const int d0 = tid * 4;
    const float4 b2v = *(const float4*)(b2 + d0);
    unsigned long long acc[4][2] = {};
    const float4* w2p = (const float4*)w2;
#pragma unroll 4
    for (int k = 0; k < 64; k++) {
        float4 w = w2p[k * 256 + tid];
        unsigned long long wl = pk2(w.x, w.y), wh = pk2(w.z, w.w);
#pragma unroll
        for (int r = 0; r < 4; r++) {
            unsigned long long g2 = sgd[r * 64 + k];
            fma2(acc[r][0], g2, wl);
            fma2(acc[r][1], g2, wh);
        }
    }

#pragma unroll
    for (int r = 0; r < 4; r++) {
        int row = row0 + r;
        int b = row / Nn, n = row - b * Nn;
        size_t off = ((size_t)(n * Bn + b) << 10) + d0;
        float4 xv = *(const float4*)(x + off);
        float a0, a1, a2, a3;
        upk2(acc[r][0], a0, a1);
        upk2(acc[r][1], a2, a3);
        float4 o;
        o.x = xv.x + b2v.x + a0;
        o.y = xv.y + b2v.y + a1;
        o.z = xv.z + b2v.z + a2;
        o.w = xv.w + b2v.w + a3;
        *(float4*)(out + off) = o;
    }
}

// ======================================================================
extern "C" void kernel_launch(void* const* d_in, const int* in_sizes, int n_in,
                              void* d_out, int out_size)
{
    (void)in_sizes; (void)n_in; (void)out_size;
    const float* x     = (const float*)d_in[0];
    const float* ln_w  = (const float*)d_in[1];
    const float* ln_b  = (const float*)d_in[2];
    const float* gamma = (const float*)d_in[3];
    const float* gmx   = (const float*)d_in[4];
    const float* w1    = (const float*)d_in[5];
    const float* b1    = (const float*)d_in[6];
    const float* w2    = (const float*)d_in[7];
    const float* b2    = (const float*)d_in[8];
    const float* dw3w  = (const float*)d_in[9];
    const float* dw3b  = (const float*)d_in[10];
    const float* dw5w  = (const float*)d_in[11];
    const float* dw5b  = (const float*)d_in[12];
    const float* dw7w  = (const float*)d_in[13];
    const float* dw7b  = (const float*)d_in[14];
    const float* projw = (const float*)d_in[15];
    const float* projb = (const float*)d_in[16];
    float* out = (float*)d_out;

    // 65600 rows total, 4 per block
    k1_ln_gemm1<<<16400, 256>>>(x, ln_w, ln_b, gamma, gmx, w1, b1);
    k2_dwconv<<<dim3(16, 64), 256>>>(dw3w, dw3b, dw5w, dw5b, dw7w, dw7b);
    k_cls_gelu<<<16, 256>>>();
    k3_proj_gelu<<<2048, 256>>>(projw, projb);
    k4_gemm2<<<16400, 256>>>(x, w2, b2, out);
}